// round 3
// baseline (speedup 1.0000x reference)
#include <cuda_runtime.h>
#include <cstdint>
#include <math.h>

// Problem constants
#define BB 8
#define TT 4096
#define DD 512
#define HH 512
#define MTOT (BB*TT)          // 32768 rows
#define NTOK (BB*TT)          // tokens

// ---------------- scratch (static device globals; no allocation) -------------
__device__ __align__(16) float g_h[(size_t)MTOT * HH];   // 64 MB
__device__ float g_div[256];
__device__ int   g_mask[NTOK];
__device__ int   g_sel[NTOK];
__device__ int   g_lens[BB];

// ---------------- threefry2x32 (Random123 / JAX-compatible) ------------------
__host__ __device__ __forceinline__
void threefry2x32(uint32_t k0, uint32_t k1, uint32_t x0, uint32_t x1,
                  uint32_t& o0, uint32_t& o1)
{
    uint32_t ks2 = k0 ^ k1 ^ 0x1BD11BDAu;
    x0 += k0; x1 += k1;
#define RND(r) { x0 += x1; x1 = (x1 << r) | (x1 >> (32 - r)); x1 ^= x0; }
    RND(13) RND(15) RND(26) RND(6)
    x0 += k1; x1 += ks2 + 1u;
    RND(17) RND(29) RND(16) RND(24)
    x0 += ks2; x1 += k0 + 2u;
    RND(13) RND(15) RND(26) RND(6)
    x0 += k0; x1 += k1 + 3u;
    RND(17) RND(29) RND(16) RND(24)
    x0 += k1; x1 += ks2 + 4u;
    RND(13) RND(15) RND(26) RND(6)
    x0 += ks2; x1 += k0 + 5u;
#undef RND
    o0 = x0; o1 = x1;
}

// gumbel draw matching jax.random.gumbel under jax_threefry_partitionable=True:
// per-element uint64 counter = flat index i (row-major over [512,64,2]);
// 32-bit draw = bits1 ^ bits2 of threefry2x32(key, (hi32(i)=0, lo32(i)=i)).
__device__ __forceinline__
float gumbel_at(uint32_t k0, uint32_t k1, uint32_t idx)
{
    uint32_t o0, o1;
    threefry2x32(k0, k1, 0u, idx, o0, o1);
    uint32_t bits = o0 ^ o1;
    uint32_t fb = (bits >> 9) | 0x3f800000u;
    float f = __uint_as_float(fb) - 1.0f;
    // uniform(minval=tiny, maxval=1):  u = max(f, tiny)
    float u = fmaxf(f, 1.17549435e-38f);
    // -log(-log(u)) with intermediate rounding to f32
    float l1 = (float)log((double)u);
    float g  = -(float)log((double)(-l1));
    return g;
}

// ---------------- K0: inv-freq table (bit-exact vs XLA's CR expf) ------------
__global__ void div_kernel()
{
    int j = threadIdx.x;   // 0..255
    double c = -log(10000.0) / 512.0;
    float arg = (float)(2 * j) * (float)c;   // matches arange(0,512,2,f32) * f32(c)
    g_div[j] = (float)exp((double)arg);      // == correctly-rounded expf(arg)
}

// ---------------- K1: h = (data @ W_embed + b + PE) * 8 ---------------------
__global__ __launch_bounds__(256)
void gemm_pe_kernel(const float* __restrict__ A,      // [32768, 512]
                    const float* __restrict__ W,      // [512, 512]
                    const float* __restrict__ bias)   // [512]
{
    __shared__ float As[8][128];
    __shared__ float Bs[8][128];

    const int bn = blockIdx.x;   // 0..3
    const int bm = blockIdx.y;   // 0..255
    const int tid = threadIdx.x;
    const int tx = tid & 15;
    const int ty = tid >> 4;
    const int m0 = bm * 128, n0 = bn * 128;

    float acc[8][8];
#pragma unroll
    for (int i = 0; i < 8; i++)
#pragma unroll
        for (int j = 0; j < 8; j++) acc[i][j] = 0.f;

    const int arow = tid >> 1;
    const int ak   = (tid & 1) << 2;
    const int brow = tid >> 5;
    const int bcol = (tid & 31) << 2;

    const float* Aptr = A + (size_t)(m0 + arow) * 512 + ak;
    const float* Wptr = W + (size_t)brow * 512 + n0 + bcol;

    for (int k0 = 0; k0 < 512; k0 += 8) {
        float4 av = *(const float4*)(Aptr + k0);
        As[ak + 0][arow] = av.x;
        As[ak + 1][arow] = av.y;
        As[ak + 2][arow] = av.z;
        As[ak + 3][arow] = av.w;
        float4 bv = *(const float4*)(Wptr + (size_t)k0 * 512);
        *(float4*)&Bs[brow][bcol] = bv;
        __syncthreads();
#pragma unroll
        for (int kk = 0; kk < 8; kk++) {
            float ra[8], rb[8];
            *(float4*)&ra[0] = *(const float4*)&As[kk][ty * 8];
            *(float4*)&ra[4] = *(const float4*)&As[kk][ty * 8 + 4];
            *(float4*)&rb[0] = *(const float4*)&Bs[kk][tx * 8];
            *(float4*)&rb[4] = *(const float4*)&Bs[kk][tx * 8 + 4];
#pragma unroll
            for (int i = 0; i < 8; i++)
#pragma unroll
                for (int j = 0; j < 8; j++)
                    acc[i][j] = fmaf(ra[i], rb[j], acc[i][j]);
        }
        __syncthreads();
    }

    // epilogue: + bias + sinusoidal PE, * sqrt(64)
#pragma unroll
    for (int i = 0; i < 8; i++) {
        int m = m0 + ty * 8 + i;
        int t = m & 4095;
        float tf = (float)t;
        float* outp = g_h + (size_t)m * 512;
#pragma unroll
        for (int j = 0; j < 8; j++) {
            int n = n0 + tx * 8 + j;
            float inv = g_div[n >> 1];
            float ang = tf * inv;            // bit-exact vs reference's fp32 pos*div
            float pe  = (n & 1) ? cosf(ang) : sinf(ang);
            outp[n] = ((acc[i][j] + bias[n]) + pe) * 8.0f;
        }
    }
}

// ---------------- K2: logits + gumbel-max decisions --> mask -----------------
__global__ __launch_bounds__(256)
void filter_kernel(const float* __restrict__ Wx,   // [512,2]
                   const float* __restrict__ Wv,   // [512,2]
                   const float* __restrict__ bf,   // [2]
                   const float* __restrict__ v0,   // [8,512]
                   const float* __restrict__ v1,   // [8,512]
                   uint32_t ka0, uint32_t ka1, uint32_t kb0, uint32_t kb1)
{
    const int bc    = blockIdx.x;   // 0..511 chunk rows
    const int b     = bc >> 6;
    const int chunk = bc & 63;
    const int tid   = threadIdx.x;

    __shared__ float4 wx0v[128], wx1v[128];
    __shared__ double cb[2][2];
    float* wx0s = (float*)wx0v;
    float* wx1s = (float*)wx1v;

    for (int k = tid; k < 512; k += 256) {
        wx0s[k] = Wx[2 * k];
        wx1s[k] = Wx[2 * k + 1];
    }

    if (tid < 32) {
        // v @ Wv in double for near-exact logits (flip-risk reduction)
        double s00 = 0, s01 = 0, s10 = 0, s11 = 0;
        for (int k = tid; k < 512; k += 32) {
            double w0 = Wv[2 * k], w1 = Wv[2 * k + 1];
            double a = v0[b * 512 + k], c = v1[b * 512 + k];
            s00 += a * w0; s01 += a * w1;
            s10 += c * w0; s11 += c * w1;
        }
#pragma unroll
        for (int off = 16; off; off >>= 1) {
            s00 += __shfl_xor_sync(0xffffffffu, s00, off);
            s01 += __shfl_xor_sync(0xffffffffu, s01, off);
            s10 += __shfl_xor_sync(0xffffffffu, s10, off);
            s11 += __shfl_xor_sync(0xffffffffu, s11, off);
        }
        if (tid == 0) {
            cb[0][0] = s00 + (double)bf[0]; cb[0][1] = s01 + (double)bf[1];
            cb[1][0] = s10 + (double)bf[0]; cb[1][1] = s11 + (double)bf[1];
        }
    }
    __syncthreads();

    const int warp = tid >> 5, lane = tid & 31;
    for (int tl = warp; tl < 64; tl += 8) {
        int t = chunk * 64 + tl;
        const float4* hp = (const float4*)(g_h + ((size_t)(b * 4096 + t) << 9));
        double d0 = 0., d1 = 0.;
#pragma unroll
        for (int r = 0; r < 4; r++) {
            float4 x  = hp[lane + 32 * r];
            float4 w0 = wx0v[lane + 32 * r];
            float4 w1 = wx1v[lane + 32 * r];
            d0 += (double)x.x * w0.x + (double)x.y * w0.y
                + (double)x.z * w0.z + (double)x.w * w0.w;
            d1 += (double)x.x * w1.x + (double)x.y * w1.y
                + (double)x.z * w1.z + (double)x.w * w1.w;
        }
#pragma unroll
        for (int off = 16; off; off >>= 1) {
            d0 += __shfl_xor_sync(0xffffffffu, d0, off);
            d1 += __shfl_xor_sync(0xffffffffu, d1, off);
        }
        if (lane == 0) {
            uint32_t base = (uint32_t)(b * 8192 + 2 * t);   // flat idx into [512,64,2]
            float g00 = gumbel_at(ka0, ka1, base);
            float g01 = gumbel_at(ka0, ka1, base + 1u);
            float g10 = gumbel_at(kb0, kb1, base);
            float g11 = gumbel_at(kb0, kb1, base + 1u);
            // logits rounded to f32 (reference materializes f32 logits), then + gumbel
            float l00 = (float)(d0 + cb[0][0]), l01 = (float)(d1 + cb[0][1]);
            float l10 = (float)(d0 + cb[1][0]), l11 = (float)(d1 + cb[1][1]);
            int f0 = ((l00 + g00) >= (l01 + g01));
            int f1 = ((l10 + g10) >= (l11 + g11));
            g_mask[b * 4096 + t] = f0 & f1;
        }
    }
}

// ---------------- K3: per-row stable exclusive scan --> sel indices ----------
__global__ __launch_bounds__(256)
void scan_kernel()
{
    const int b = blockIdx.x;    // 8 blocks
    const int tid = threadIdx.x; // 256 threads, 16 tokens each (contiguous)
    const int base = tid * 16;

    int m[16];
    int cnt = 0;
#pragma unroll
    for (int q = 0; q < 16; q++) {
        m[q] = g_mask[b * 4096 + base + q];
        cnt += m[q];
    }

    const int lane = tid & 31, warp = tid >> 5;
    int v = cnt;
#pragma unroll
    for (int off = 1; off < 32; off <<= 1) {
        int n2 = __shfl_up_sync(0xffffffffu, v, off);
        if (lane >= off) v += n2;
    }
    __shared__ int wtot[8];
    if (lane == 31) wtot[warp] = v;
    __syncthreads();
    int woff = 0;
    for (int w = 0; w < warp; w++) woff += wtot[w];
    int excl = woff + v - cnt;

    int pos = excl;
#pragma unroll
    for (int q = 0; q < 16; q++) {
        if (m[q]) g_sel[b * 4096 + pos++] = base + q;
    }
    if (tid == 255) g_lens[b] = excl + cnt;
}

// ---------------- K4: gather / pad -------------------------------------------
__global__ __launch_bounds__(128)
void gather_kernel(float* __restrict__ out)
{
    const int b = blockIdx.y;
    const int k = blockIdx.x;
    const int tid = threadIdx.x;   // 128 threads * float4 = 512 floats
    float4* o = (float4*)out + ((size_t)(b * 4096 + k) << 7);
    if (k < g_lens[b]) {
        int t = g_sel[b * 4096 + k];
        const float4* hp = (const float4*)g_h + ((size_t)(b * 4096 + t) << 7);
        o[tid] = hp[tid];
    } else {
        o[tid] = make_float4(0.f, 0.f, 0.f, 0.f);
    }
}

// ---------------- launch ------------------------------------------------------
extern "C" void kernel_launch(void* const* d_in, const int* in_sizes, int n_in,
                              void* d_out, int out_size)
{
    const float* data    = (const float*)d_in[0];
    const float* v0      = (const float*)d_in[1];
    const float* v1      = (const float*)d_in[2];
    const float* W_embed = (const float*)d_in[3];
    const float* b_embed = (const float*)d_in[4];
    const float* Wx      = (const float*)d_in[5];
    const float* Wv      = (const float*)d_in[6];
    const float* b_f     = (const float*)d_in[7];
    float* out = (float*)d_out;

    // folded keys: fold_in(key(42), i) == threefry2x32(key=(0,42), x=(0,i))
    uint32_t ka0, ka1, kb0, kb1;
    threefry2x32(0u, 42u, 0u, 0u, ka0, ka1);
    threefry2x32(0u, 42u, 0u, 1u, kb0, kb1);

    div_kernel<<<1, 256>>>();
    gemm_pe_kernel<<<dim3(4, 256), 256>>>(data, W_embed, b_embed);
    filter_kernel<<<512, 256>>>(Wx, Wv, b_f, v0, v1, ka0, ka1, kb0, kb1);
    scan_kernel<<<8, 256>>>();
    gather_kernel<<<dim3(4096, 8), 128>>>(out);
}

// round 8
// speedup vs baseline: 1.2091x; 1.2091x over previous
#include <cuda_runtime.h>
#include <cuda_bf16.h>
#include <cstdint>
#include <math.h>

// Problem constants
#define BB 8
#define TT 4096
#define HH 512
#define MTOT (BB*TT)          // 32768 rows

// ---------------- scratch (static device globals; no allocation) -------------
__device__ __align__(16) float g_h[(size_t)MTOT * HH];     // 64 MB
__device__ __align__(16) float g_pe[(size_t)TT * HH];      // 8 MB
__device__ float g_div[256];
__device__ int   g_mask[MTOT];
__device__ int   g_sel[MTOT];
__device__ int   g_lens[BB];
__device__ __align__(16) __nv_bfloat16 g_A1[(size_t)MTOT * HH];  // 32 MB each
__device__ __align__(16) __nv_bfloat16 g_A2[(size_t)MTOT * HH];
__device__ __align__(16) __nv_bfloat16 g_A3[(size_t)MTOT * HH];
__device__ __align__(16) __nv_bfloat16 g_W1[HH * HH];            // transposed [n][k]
__device__ __align__(16) __nv_bfloat16 g_W2[HH * HH];
__device__ __align__(16) __nv_bfloat16 g_W3[HH * HH];

// ---------------- helpers ----------------------------------------------------
__device__ __forceinline__ uint32_t smem_to_u32(const void* p) {
    uint32_t a;
    asm("{ .reg .u64 t; cvta.to.shared.u64 t, %1; cvt.u32.u64 %0, t; }" : "=r"(a) : "l"(p));
    return a;
}
__device__ __forceinline__ void cpasync16(uint32_t sa, const void* g) {
    asm volatile("cp.async.cg.shared.global [%0], [%1], 16;" :: "r"(sa), "l"(g));
}
__device__ __forceinline__ void ldm_x4(uint32_t* r, uint32_t addr) {
    asm volatile("ldmatrix.sync.aligned.m8n8.x4.shared.b16 {%0,%1,%2,%3}, [%4];"
        : "=r"(r[0]), "=r"(r[1]), "=r"(r[2]), "=r"(r[3]) : "r"(addr));
}
__device__ __forceinline__ void mma16816(float* d, const uint32_t* a,
                                         uint32_t b0, uint32_t b1) {
    asm volatile("mma.sync.aligned.m16n8k16.row.col.f32.bf16.bf16.f32 "
        "{%0,%1,%2,%3}, {%4,%5,%6,%7}, {%8,%9}, {%0,%1,%2,%3};"
        : "+f"(d[0]), "+f"(d[1]), "+f"(d[2]), "+f"(d[3])
        : "r"(a[0]), "r"(a[1]), "r"(a[2]), "r"(a[3]), "r"(b0), "r"(b1));
}

// ---------------- threefry2x32 (Random123 / JAX-compatible) ------------------
__host__ __device__ __forceinline__
void threefry2x32(uint32_t k0, uint32_t k1, uint32_t x0, uint32_t x1,
                  uint32_t& o0, uint32_t& o1)
{
    uint32_t ks2 = k0 ^ k1 ^ 0x1BD11BDAu;
    x0 += k0; x1 += k1;
#define RND(r) { x0 += x1; x1 = (x1 << r) | (x1 >> (32 - r)); x1 ^= x0; }
    RND(13) RND(15) RND(26) RND(6)
    x0 += k1; x1 += ks2 + 1u;
    RND(17) RND(29) RND(16) RND(24)
    x0 += ks2; x1 += k0 + 2u;
    RND(13) RND(15) RND(26) RND(6)
    x0 += k0; x1 += k1 + 3u;
    RND(17) RND(29) RND(16) RND(24)
    x0 += k1; x1 += ks2 + 4u;
    RND(13) RND(15) RND(26) RND(6)
    x0 += ks2; x1 += k0 + 5u;
#undef RND
    o0 = x0; o1 = x1;
}

// gumbel draw, jax_threefry_partitionable=True: bits = o0 ^ o1 of (key, (0, idx))
__device__ __forceinline__
float gumbel_at(uint32_t k0, uint32_t k1, uint32_t idx)
{
    uint32_t o0, o1;
    threefry2x32(k0, k1, 0u, idx, o0, o1);
    uint32_t bits = o0 ^ o1;
    uint32_t fb = (bits >> 9) | 0x3f800000u;
    float f = __uint_as_float(fb) - 1.0f;
    float u = fmaxf(f, 1.17549435e-38f);
    float l1 = (float)log((double)u);
    return -(float)log((double)(-l1));
}

// ---------------- K0a: inv-freq table ----------------------------------------
__global__ void div_kernel()
{
    int j = threadIdx.x;
    double c = -log(10000.0) / 512.0;
    float arg = (float)(2 * j) * (float)c;
    g_div[j] = (float)exp((double)arg);
}

// ---------------- K0b: PE table [4096, 512] ----------------------------------
__global__ __launch_bounds__(256) void pe_kernel()
{
    int t = blockIdx.x;
    float tf = (float)t;
    for (int n = threadIdx.x; n < 512; n += 256) {
        float ang = tf * g_div[n >> 1];
        g_pe[(size_t)t * 512 + n] = (n & 1) ? cosf(ang) : sinf(ang);
    }
}

// ---------------- K0c: split data into 3 bf16 terms --------------------------
__global__ __launch_bounds__(256)
void splitA_kernel(const float4* __restrict__ in)
{
    size_t idx = (size_t)blockIdx.x * 256 + threadIdx.x;   // 4,194,304 total
    float4 v = in[idx];
    float x[4] = {v.x, v.y, v.z, v.w};
    __nv_bfloat16 h1[4], h2[4], h3[4];
#pragma unroll
    for (int i = 0; i < 4; i++) {
        h1[i] = __float2bfloat16(x[i]);
        float r = x[i] - __bfloat162float(h1[i]);
        h2[i] = __float2bfloat16(r);
        float r2 = r - __bfloat162float(h2[i]);
        h3[i] = __float2bfloat16(r2);
    }
    uint2 u;
    __nv_bfloat162 p;
#define PACK(dst, h) \
    p = __halves2bfloat162((h)[0], (h)[1]); u.x = *(uint32_t*)&p; \
    p = __halves2bfloat162((h)[2], (h)[3]); u.y = *(uint32_t*)&p; \
    *(uint2*)((dst) + idx * 4) = u;
    PACK(g_A1, h1) PACK(g_A2, h2) PACK(g_A3, h3)
#undef PACK
}

// ---------------- K0d: split + transpose W into bf16 [n][k] ------------------
__global__ void splitW_kernel(const float* __restrict__ W)
{
    __shared__ float ts[32][33];
    int kt = blockIdx.y * 32, nt = blockIdx.x * 32;
    int tx = threadIdx.x, ty = threadIdx.y;   // 32 x 8
    for (int i = ty; i < 32; i += 8)
        ts[i][tx] = W[(size_t)(kt + i) * 512 + nt + tx];
    __syncthreads();
    for (int i = ty; i < 32; i += 8) {
        float x = ts[tx][i];   // = W[kt+tx][nt+i]
        __nv_bfloat16 h1 = __float2bfloat16(x);
        float r = x - __bfloat162float(h1);
        __nv_bfloat16 h2 = __float2bfloat16(r);
        float r2 = r - __bfloat162float(h2);
        __nv_bfloat16 h3 = __float2bfloat16(r2);
        size_t o = (size_t)(nt + i) * 512 + kt + tx;
        g_W1[o] = h1; g_W2[o] = h2; g_W3[o] = h3;
    }
}

// ---------------- K1: mma.sync bf16x3 GEMM + PE epilogue ---------------------
// CTA 128x128, 256 thr (8 warps, warp 32x64), K chunks of 32, double-buffered.
// SMEM rows padded to 40 bf16 (80B) -> conflict-free ldmatrix, 16B aligned.
#define ROWB 80
#define MATB (128 * ROWB)          // 10240 B per matrix
#define STAGEB (6 * MATB)          // 61440 B per stage (A1..3, W1..3)
#define GEMM_SMEM (2 * STAGEB)     // 122880 B

__global__ __launch_bounds__(256, 1)
void mma_gemm_kernel(const float* __restrict__ bias)
{
    extern __shared__ char smem[];
    const uint32_t sb = smem_to_u32(smem);
    const int tid = threadIdx.x;
    const int n0 = blockIdx.x * 128;
    const int m0 = blockIdx.y * 128;
    const int lane = tid & 31;
    const int w = tid >> 5;
    const int wm = w & 3;          // 4 m-strips of 32
    const int wn = w >> 2;         // 2 n-strips of 64

    const __nv_bfloat16* gmat[6] = {g_A1, g_A2, g_A3, g_W1, g_W2, g_W3};

    // --- async copy of one K-chunk (A:3 + B:3 matrices, 128x32 bf16 each) ----
    auto issue_copy = [&](int ch, int st) {
        const int k0 = ch * 32;
#pragma unroll
        for (int it = 0; it < 12; it++) {
            int idx = tid + it * 256;           // 0..3071
            int mi = idx >> 9;                  // matrix 0..5
            int r  = (idx >> 2) & 127;          // row in tile
            int c  = idx & 3;                   // 16B chunk in row
            int grow = ((mi < 3) ? m0 : n0) + r;
            const __nv_bfloat16* gp = gmat[mi] + (size_t)grow * 512 + k0 + c * 8;
            cpasync16(sb + st * STAGEB + mi * MATB + r * ROWB + c * 16, gp);
        }
        asm volatile("cp.async.commit_group;" ::: "memory");
    };

    float facc[2][8][4];
#pragma unroll
    for (int a = 0; a < 2; a++)
#pragma unroll
        for (int b = 0; b < 8; b++)
#pragma unroll
            for (int c = 0; c < 4; c++) facc[a][b][c] = 0.f;

    issue_copy(0, 0);

    const int rsel = lane & 15;
    const int chalf = (lane >> 4) << 4;     // 0 or 16 bytes

    for (int ch = 0; ch < 16; ch++) {
        const int st = ch & 1;
        asm volatile("cp.async.wait_group 0;" ::: "memory");
        __syncthreads();
        if (ch < 15) issue_copy(ch + 1, st ^ 1);

        const uint32_t bst = sb + st * STAGEB;
#pragma unroll
        for (int ks = 0; ks < 2; ks++) {
            const int colb = ks * 32 + chalf;
            uint32_t fa[3][2][4], fb[3][4][4];
#pragma unroll
            for (int sp = 0; sp < 3; sp++) {
#pragma unroll
                for (int mt = 0; mt < 2; mt++)
                    ldm_x4(fa[sp][mt],
                           bst + sp * MATB + (wm * 32 + mt * 16 + rsel) * ROWB + colb);
#pragma unroll
                for (int ng = 0; ng < 4; ng++)
                    ldm_x4(fb[sp][ng],
                           bst + (3 + sp) * MATB + (wn * 64 + ng * 16 + rsel) * ROWB + colb);
            }
            const int pa[6] = {0, 0, 1, 1, 0, 2};
            const int pb[6] = {0, 1, 0, 1, 2, 0};
#pragma unroll
            for (int p = 0; p < 6; p++)
#pragma unroll
                for (int mt = 0; mt < 2; mt++)
#pragma unroll
                    for (int ng = 0; ng < 4; ng++) {
                        mma16816(facc[mt][ng * 2 + 0], fa[pa[p]][mt],
                                 fb[pb[p]][ng][0], fb[pb[p]][ng][2]);
                        mma16816(facc[mt][ng * 2 + 1], fa[pa[p]][mt],
                                 fb[pb[p]][ng][1], fb[pb[p]][ng][3]);
                    }
        }
        __syncthreads();
    }

    // epilogue: + bias + PE, * 8, direct float2 stores (32B sectors per quad)
#pragma unroll
    for (int mt = 0; mt < 2; mt++)
#pragma unroll
        for (int nt = 0; nt < 8; nt++) {
            int m = m0 + wm * 32 + mt * 16 + (lane >> 2);
            int n = n0 + wn * 64 + nt * 8 + (lane & 3) * 2;
            float b0 = bias[n], b1 = bias[n + 1];
            const float* pe0 = g_pe + (size_t)(m & 4095) * 512 + n;
            float2 v;
            v.x = (facc[mt][nt][0] + b0 + pe0[0]) * 8.0f;
            v.y = (facc[mt][nt][1] + b1 + pe0[1]) * 8.0f;
            *(float2*)(g_h + (size_t)m * 512 + n) = v;
            const float* pe1 = g_pe + (size_t)((m + 8) & 4095) * 512 + n;
            v.x = (facc[mt][nt][2] + b0 + pe1[0]) * 8.0f;
            v.y = (facc[mt][nt][3] + b1 + pe1[1]) * 8.0f;
            *(float2*)(g_h + (size_t)(m + 8) * 512 + n) = v;
        }
}

// ---------------- K2: logits + gumbel-max decisions --> mask -----------------
__global__ __launch_bounds__(256)
void filter_kernel(const float* __restrict__ Wx,   // [512,2]
                   const float* __restrict__ Wv,   // [512,2]
                   const float* __restrict__ bf,   // [2]
                   const float* __restrict__ v0,   // [8,512]
                   const float* __restrict__ v1,   // [8,512]
                   uint32_t ka0, uint32_t ka1, uint32_t kb0, uint32_t kb1)
{
    const int bc    = blockIdx.x;   // 0..511 chunk rows
    const int b     = bc >> 6;
    const int chunk = bc & 63;
    const int tid   = threadIdx.x;

    __shared__ float4 wx0v[128], wx1v[128];
    __shared__ double cb[2][2];
    float* wx0s = (float*)wx0v;
    float* wx1s = (float*)wx1v;

    for (int k = tid; k < 512; k += 256) {
        wx0s[k] = Wx[2 * k];
        wx1s[k] = Wx[2 * k + 1];
    }

    if (tid < 32) {
        double s00 = 0, s01 = 0, s10 = 0, s11 = 0;
        for (int k = tid; k < 512; k += 32) {
            double w0 = Wv[2 * k], w1 = Wv[2 * k + 1];
            double a = v0[b * 512 + k], c = v1[b * 512 + k];
            s00 += a * w0; s01 += a * w1;
            s10 += c * w0; s11 += c * w1;
        }
#pragma unroll
        for (int off = 16; off; off >>= 1) {
            s00 += __shfl_xor_sync(0xffffffffu, s00, off);
            s01 += __shfl_xor_sync(0xffffffffu, s01, off);
            s10 += __shfl_xor_sync(0xffffffffu, s10, off);
            s11 += __shfl_xor_sync(0xffffffffu, s11, off);
        }
        if (tid == 0) {
            cb[0][0] = s00 + (double)bf[0]; cb[0][1] = s01 + (double)bf[1];
            cb[1][0] = s10 + (double)bf[0]; cb[1][1] = s11 + (double)bf[1];
        }
    }
    __syncthreads();

    const int warp = tid >> 5, lane = tid & 31;
    for (int tl = warp; tl < 64; tl += 8) {
        int t = chunk * 64 + tl;
        const float4* hp = (const float4*)(g_h + ((size_t)(b * 4096 + t) << 9));
        // Kahan-compensated fp32 accumulation (error ~1e-7 abs)
        float d0 = 0.f, c0 = 0.f, d1 = 0.f, c1 = 0.f;
#pragma unroll
        for (int r = 0; r < 4; r++) {
            float4 x  = hp[lane + 32 * r];
            float4 w0 = wx0v[lane + 32 * r];
            float4 w1 = wx1v[lane + 32 * r];
            float p0 = x.x * w0.x + x.y * w0.y + x.z * w0.z + x.w * w0.w;
            float p1 = x.x * w1.x + x.y * w1.y + x.z * w1.z + x.w * w1.w;
            float y0 = p0 - c0, t0 = d0 + y0; c0 = (t0 - d0) - y0; d0 = t0;
            float y1 = p1 - c1, t1 = d1 + y1; c1 = (t1 - d1) - y1; d1 = t1;
        }
        d0 += c0; d1 += c1;
#pragma unroll
        for (int off = 16; off; off >>= 1) {
            d0 += __shfl_xor_sync(0xffffffffu, d0, off);
            d1 += __shfl_xor_sync(0xffffffffu, d1, off);
        }
        if (lane == 0) {
            uint32_t base = (uint32_t)(b * 8192 + 2 * t);
            float g00 = gumbel_at(ka0, ka1, base);
            float g01 = gumbel_at(ka0, ka1, base + 1u);
            float g10 = gumbel_at(kb0, kb1, base);
            float g11 = gumbel_at(kb0, kb1, base + 1u);
            float l00 = (float)((double)d0 + cb[0][0]), l01 = (float)((double)d1 + cb[0][1]);
            float l10 = (float)((double)d0 + cb[1][0]), l11 = (float)((double)d1 + cb[1][1]);
            int f0 = ((l00 + g00) >= (l01 + g01));
            int f1 = ((l10 + g10) >= (l11 + g11));
            g_mask[b * 4096 + t] = f0 & f1;
        }
    }
}

// ---------------- K3: per-row stable exclusive scan --> sel indices ----------
__global__ __launch_bounds__(256)
void scan_kernel()
{
    const int b = blockIdx.x;
    const int tid = threadIdx.x;
    const int base = tid * 16;

    int m[16];
    int cnt = 0;
#pragma unroll
    for (int q = 0; q < 16; q++) {
        m[q] = g_mask[b * 4096 + base + q];
        cnt += m[q];
    }

    const int lane = tid & 31, warp = tid >> 5;
    int v = cnt;
#pragma unroll
    for (int off = 1; off < 32; off <<= 1) {
        int n2 = __shfl_up_sync(0xffffffffu, v, off);
        if (lane >= off) v += n2;
    }
    __shared__ int wtot[8];
    if (lane == 31) wtot[warp] = v;
    __syncthreads();
    int woff = 0;
    for (int w = 0; w < warp; w++) woff += wtot[w];
    int excl = woff + v - cnt;

    int pos = excl;
#pragma unroll
    for (int q = 0; q < 16; q++) {
        if (m[q]) g_sel[b * 4096 + pos++] = base + q;
    }
    if (tid == 255) g_lens[b] = excl + cnt;
}

// ---------------- K4: gather / pad -------------------------------------------
__global__ __launch_bounds__(128)
void gather_kernel(float* __restrict__ out)
{
    const int b = blockIdx.y;
    const int k = blockIdx.x;
    const int tid = threadIdx.x;
    float4* o = (float4*)out + ((size_t)(b * 4096 + k) << 7);
    if (k < g_lens[b]) {
        int t = g_sel[b * 4096 + k];
        const float4* hp = (const float4*)g_h + ((size_t)(b * 4096 + t) << 7);
        o[tid] = hp[tid];
    } else {
        o[tid] = make_float4(0.f, 0.f, 0.f, 0.f);
    }
}

// ---------------- launch ------------------------------------------------------
extern "C" void kernel_launch(void* const* d_in, const int* in_sizes, int n_in,
                              void* d_out, int out_size)
{
    const float* data    = (const float*)d_in[0];
    const float* v0      = (const float*)d_in[1];
    const float* v1      = (const float*)d_in[2];
    const float* W_embed = (const float*)d_in[3];
    const float* b_embed = (const float*)d_in[4];
    const float* Wx      = (const float*)d_in[5];
    const float* Wv      = (const float*)d_in[6];
    const float* b_f     = (const float*)d_in[7];
    float* out = (float*)d_out;

    uint32_t ka0, ka1, kb0, kb1;
    threefry2x32(0u, 42u, 0u, 0u, ka0, ka1);
    threefry2x32(0u, 42u, 0u, 1u, kb0, kb1);

    cudaFuncSetAttribute(mma_gemm_kernel,
                         cudaFuncAttributeMaxDynamicSharedMemorySize, GEMM_SMEM);

    div_kernel<<<1, 256>>>();
    pe_kernel<<<4096, 256>>>();
    splitA_kernel<<<16384, 256>>>((const float4*)data);
    splitW_kernel<<<dim3(16, 16), dim3(32, 8)>>>(W_embed);
    mma_gemm_kernel<<<dim3(4, 256), 256, GEMM_SMEM>>>(b_embed);
    filter_kernel<<<512, 256>>>(Wx, Wv, b_f, v0, v1, ka0, ka1, kb0, kb1);
    scan_kernel<<<8, 256>>>();
    gather_kernel<<<dim3(4096, 8), 128>>>(out);
}